// round 1
// baseline (speedup 1.0000x reference)
#include <cuda_runtime.h>
#include <cstdint>

#define BB 256
#define TT 512
#define CC 128

// Scratch (allocations are forbidden): backpointers [T-1][B][C] u8 (~16.7MB), final tags.
__device__ uint4 g_bp4[((TT - 1) * BB * CC) / 16];
__device__ int g_final_tag[BB];

// ---------------------------------------------------------------------------
// Forward pass: one CTA per batch, thread j owns state j.
//   cur[j] = max_i(prev[i] + trans[i][j]) + em[t][j]
// trans column j in registers (tc[128]); full trans in dynamic smem for the
// 8-element exact argmax rescan. prev double-buffered in smem, 1 bar/step.
// ---------------------------------------------------------------------------
__global__ __launch_bounds__(CC, 2)
void viterbi_fwd(const float* __restrict__ em,
                 const float* __restrict__ trans,
                 float* __restrict__ out)
{
    extern __shared__ float s_trans[];               // CC*CC floats = 64KB
    __shared__ __align__(16) float s_prev[2][CC];

    const int b = blockIdx.x;
    const int j = threadIdx.x;

    // Stage transition matrix into smem (for phase-2 dynamic-index reads).
    for (int idx = j; idx < CC * CC; idx += CC)
        s_trans[idx] = trans[idx];

    // Own column of trans in registers (constant indices after full unroll).
    float tc[CC];
#pragma unroll
    for (int i = 0; i < CC; ++i)
        tc[i] = trans[i * CC + j];

    const float* emb = em + (size_t)b * TT * CC;
    float cur = emb[j];                               // t = 0 init

    unsigned char* bp = ((unsigned char*)g_bp4) + (size_t)b * CC + j;

    __syncthreads();                                  // s_trans ready

    int buf = 0;
    for (int t = 1; t < TT; ++t) {
        s_prev[buf][j] = cur;
        float emv = emb[t * CC + j];                  // prefetch overlaps barrier
        __syncthreads();

        // -------- phase 1: 16 group maxima of 8, pure FADD + FMNMX --------
        float m[16];
#pragma unroll
        for (int g = 0; g < 16; ++g) {
            float4 p0 = *(const float4*)&s_prev[buf][g * 8];
            float4 p1 = *(const float4*)&s_prev[buf][g * 8 + 4];
            float a0 = fmaxf(p0.x + tc[g * 8 + 0], p0.y + tc[g * 8 + 1]);
            float a1 = fmaxf(p0.z + tc[g * 8 + 2], p0.w + tc[g * 8 + 3]);
            float a2 = fmaxf(p1.x + tc[g * 8 + 4], p1.y + tc[g * 8 + 5]);
            float a3 = fmaxf(p1.z + tc[g * 8 + 6], p1.w + tc[g * 8 + 7]);
            m[g] = fmaxf(fmaxf(a0, a1), fmaxf(a2, a3));
        }
        float M = m[0];
#pragma unroll
        for (int g = 1; g < 16; ++g) M = fmaxf(M, m[g]);

        // -------- phase 2: exact first-occurrence argmax -------------------
        // Smallest group holding the max (descending scan keeps first equal).
        int gsel = 15;
#pragma unroll
        for (int g = 14; g >= 0; --g) gsel = (m[g] == M) ? g : gsel;

        // Within that group: recompute (bit-identical FADD) and take the
        // smallest index achieving M. Default k=7 covers "no earlier equal".
        const int base = gsel * 8;
        int arg = base + 7;
#pragma unroll
        for (int k = 6; k >= 0; --k) {
            float v = s_prev[buf][base + k] + s_trans[(base + k) * CC + j];
            arg = (v == M) ? (base + k) : arg;
        }

        cur = M + emv;
        bp[(size_t)(t - 1) * BB * CC] = (unsigned char)arg;
        buf ^= 1;
    }

    // Final per-batch argmax over states (first-occurrence tie rule).
    s_prev[buf][j] = cur;
    __syncthreads();
    if (j == 0) {
        float best = s_prev[buf][0];
        int arg = 0;
#pragma unroll 1
        for (int i = 1; i < CC; ++i) {
            float v = s_prev[buf][i];
            if (v > best) { best = v; arg = i; }
        }
        g_final_tag[b] = arg;
        out[(size_t)BB * TT + b] = best;              // final_score[b]
    }
}

// ---------------------------------------------------------------------------
// Backtrack: one CTA per batch. Bulk-stage the batch's bp slice (65KB) into
// smem (independent of tags -> fully parallel), then chase pointers in LDS.
// ---------------------------------------------------------------------------
__global__ __launch_bounds__(CC)
void viterbi_bt(float* __restrict__ out)
{
    extern __shared__ unsigned char s_bp[];           // (TT-1)*CC bytes
    __shared__ int s_path[TT];
    const int b = blockIdx.x;

    // Copy (T-1) rows of 128B each, vectorized as uint4 (8 per row).
    const int words = (TT - 1) * CC / 16;             // 4088
    uint4* dst = (uint4*)s_bp;
    for (int idx = threadIdx.x; idx < words; idx += CC) {
        int t = idx >> 3;
        int w = idx & 7;
        dst[idx] = g_bp4[((size_t)t * BB + b) * (CC / 16) + w];
    }
    __syncthreads();

    if (threadIdx.x == 0) {
        int tag = g_final_tag[b];
        s_path[TT - 1] = tag;
        for (int t = TT - 2; t >= 0; --t) {
            tag = s_bp[t * CC + tag];
            s_path[t] = tag;
        }
    }
    __syncthreads();

    float* op = out + (size_t)b * TT;                 // path[b][t] as float
    for (int t = threadIdx.x; t < TT; t += CC)
        op[t] = (float)s_path[t];
}

// ---------------------------------------------------------------------------
// Launch: d_in[0] = emissions [B,T,C] f32, d_in[1] = transition_params [C,C].
// d_out assumed float32: path (B*T entries, integer-valued) then score (B).
// ---------------------------------------------------------------------------
extern "C" void kernel_launch(void* const* d_in, const int* in_sizes, int n_in,
                              void* d_out, int out_size)
{
    const float* em    = (const float*)d_in[0];
    const float* trans = (const float*)d_in[1];
    float* out = (float*)d_out;

    cudaFuncSetAttribute(viterbi_fwd, cudaFuncAttributeMaxDynamicSharedMemorySize,
                         CC * CC * (int)sizeof(float));
    cudaFuncSetAttribute(viterbi_bt, cudaFuncAttributeMaxDynamicSharedMemorySize,
                         (TT - 1) * CC);

    viterbi_fwd<<<BB, CC, CC * CC * sizeof(float)>>>(em, trans, out);
    viterbi_bt<<<BB, CC, (TT - 1) * CC>>>(out);
}